// round 5
// baseline (speedup 1.0000x reference)
#include <cuda_runtime.h>

#define BATCH       16384
#define NUM_FIELDS  20
#define NUM_FEAT    100000
#define LATENT      64

// Single-wave launch: 2048 CTAs x 128 threads = 8192 warps (< one full wave
// at 16 CTAs/SM), each warp handles exactly two rows (2w, 2w+1) sequentially.
// Removes the 1.73-wave tail imbalance of the one-row-per-warp launch while
// keeping the proven regs<=32 / 20x coalesced-float2-gather warp body.
// Reduction tail merged: one 5-shfl chain over (lin + 0.5*t) per row.
__global__ void __launch_bounds__(128, 16)
ffm_kernel(const int* __restrict__ x,
           const float* __restrict__ emb,
           float* __restrict__ out)
{
    const int warp = (blockIdx.x * blockDim.x + threadIdx.x) >> 5;
    const int lane = threadIdx.x & 31;

    #pragma unroll
    for (int r = 0; r < 2; r++) {
        const int row = warp * 2 + r;

        // Lanes 0..19 hold this row's feature indices (also the linear term).
        int xv = 0;
        if (lane < NUM_FIELDS) xv = __ldg(&x[row * NUM_FIELDS + lane]);

        float2 s   = make_float2(0.f, 0.f);
        float  ssq = 0.f;

        #pragma unroll
        for (int f = 0; f < NUM_FIELDS; f++) {
            const int idx = __shfl_sync(0xffffffffu, xv, f);
            const float2 v = __ldg(reinterpret_cast<const float2*>(
                emb + ((size_t)f * NUM_FEAT + (size_t)idx) * LATENT) + lane);
            s.x += v.x;
            s.y += v.y;
            ssq  = fmaf(v.x, v.x, fmaf(v.y, v.y, ssq));
        }

        // Per-lane partial of linear + 0.5*interaction; single reduce chain.
        //   sum_lanes(xv) = linear  (lanes >= 20 contribute 0)
        //   sum_lanes(t)  = |s|^2 - sum v^2 over all 64 dims
        float t   = fmaf(s.x, s.x, s.y * s.y) - ssq;
        float red = (float)xv + 0.5f * t;

        #pragma unroll
        for (int off = 16; off > 0; off >>= 1)
            red += __shfl_down_sync(0xffffffffu, red, off);

        if (lane == 0) out[row] = red;
    }
}

extern "C" void kernel_launch(void* const* d_in, const int* in_sizes, int n_in,
                              void* d_out, int out_size)
{
    const int*   x   = (const int*)d_in[0];
    // d_in[1] = field_indices (0..19), implicit in layout.
    const float* emb = (const float*)d_in[2];
    float*       out = (float*)d_out;

    const int rows_per_warp   = 2;
    const int warps_per_block = 128 / 32;                                   // 4
    const int blocks = BATCH / (warps_per_block * rows_per_warp);           // 2048
    ffm_kernel<<<blocks, 128>>>(x, emb, out);
}